// round 2
// baseline (speedup 1.0000x reference)
#include <cuda_runtime.h>
#include <math.h>

// Problem constants (shapes are fixed by the dataset: 4096 x 256 each).
#define DDIM 256
#define BM 128
#define BN 128
#define BK 8
#define TM 8
#define TN 8
#define NMAX 8192

// Scratch in __device__ globals (no allocation allowed).
__device__ double g_S;              // sum of squared norms
__device__ double g_colsum[DDIM];   // column sums of "total"
__device__ float  g_sq[NMAX];       // per-row squared norms
__device__ float  g_inv[5];         // 1/(bw * 2^i)
__device__ double g_acc;            // signed weighted kernel-sum accumulator

// ---------------------------------------------------------------------------
__global__ void k_init() {
    int t = threadIdx.x;
    if (t < DDIM) g_colsum[t] = 0.0;
    if (t == 0) { g_S = 0.0; g_acc = 0.0; }
}

// One warp per row: sq[row] = sum(x^2); also accumulate S.
__global__ void k_sq(const float* __restrict__ src,
                     const float* __restrict__ tgt, int n) {
    int row  = blockIdx.x * 8 + (threadIdx.x >> 5);
    int lane = threadIdx.x & 31;
    const float* p = (row < n) ? (src + (size_t)row * DDIM)
                               : (tgt + (size_t)(row - n) * DDIM);
    const float4* p4 = (const float4*)p;
    float s = 0.f;
#pragma unroll
    for (int i = 0; i < DDIM / 4 / 32; ++i) {
        float4 v = p4[lane + i * 32];
        s += v.x * v.x + v.y * v.y + v.z * v.z + v.w * v.w;
    }
#pragma unroll
    for (int o = 16; o; o >>= 1) s += __shfl_xor_sync(0xffffffffu, s, o);
    if (lane == 0) {
        g_sq[row] = s;
        atomicAdd(&g_S, (double)s);
    }
}

// Column sums (for ||sum_i x_i||^2). Each block covers 128 rows, 256 threads
// = 256 columns, perfectly coalesced.
__global__ void k_colsum(const float* __restrict__ src,
                         const float* __restrict__ tgt, int n) {
    int col = threadIdx.x;
    int r0  = blockIdx.x * 128;
    double s = 0.0;
    for (int r = r0; r < r0 + 128; ++r) {
        const float* p = (r < n) ? (src + (size_t)r * DDIM)
                                 : (tgt + (size_t)(r - n) * DDIM);
        s += (double)p[col];
    }
    atomicAdd(&g_colsum[col], s);
}

// Compute bandwidth analytically:
// sum(L2) = 2*N*S - 2*||colsum||^2 ;  bw = sum / (N^2-N) / 4 ; inv[i]=1/(bw*2^i)
__global__ void k_bw(int n) {
    __shared__ double sh[DDIM];
    int t = threadIdx.x;
    double v = g_colsum[t];
    sh[t] = v * v;
    __syncthreads();
    for (int o = DDIM / 2; o; o >>= 1) {
        if (t < o) sh[t] += sh[t + o];
        __syncthreads();
    }
    if (t == 0) {
        double N = 2.0 * (double)n;
        double sumL2 = 2.0 * N * g_S - 2.0 * sh[0];
        double bw = sumL2 / (N * N - N) / 4.0;  // / KERNEL_MUL^(KERNEL_NUM/2)
#pragma unroll
        for (int i = 0; i < 5; ++i)
            g_inv[i] = (float)(1.0 / (bw * (double)(1 << i)));
    }
}

// ---------------------------------------------------------------------------
// Main fused kernel. One block = one 128x128 tile of the symmetric kernel
// matrix; only upper-triangular tiles (ti <= tj) are launched. Each block
// does a 128x128x256 fp32 GEMM, then the RBF epilogue + reduction, and adds
// weight * tile_sum into g_acc:
//   weight = +1 (diag tile), +2 (off-diag within xx or yy), -2 (cross xy/yx)
__global__ void __launch_bounds__(256, 2)
k_main(const float* __restrict__ src, const float* __restrict__ tgt, int n) {
    // Linear block index -> (ti, tj) with ti <= tj (column-major triangle).
    int L  = blockIdx.x;
    int tj = (int)((sqrtf(8.0f * (float)L + 1.0f) - 1.0f) * 0.5f);
    while ((tj + 1) * (tj + 2) / 2 <= L) ++tj;
    while (tj * (tj + 1) / 2 > L) --tj;
    int ti = L - tj * (tj + 1) / 2;

    const int row0 = ti * BM;
    const int col0 = tj * BN;

    __shared__ float As[BK][BM];
    __shared__ float Bs[BK][BN];

    const int tid = threadIdx.x;
    const int tx = tid & 15;   // 0..15 -> column group
    const int ty = tid >> 4;   // 0..15 -> row group

    // Global load assignment: each thread loads one float4 of A and B per k-step.
    const int lr = tid >> 1;           // local row/col 0..127
    const int ka = (tid & 1) * 4;      // k offset 0 or 4
    const int gra = row0 + lr;
    const int grb = col0 + lr;
    const float* pA = (gra < n) ? (src + (size_t)gra * DDIM)
                                : (tgt + (size_t)(gra - n) * DDIM);
    const float* pB = (grb < n) ? (src + (size_t)grb * DDIM)
                                : (tgt + (size_t)(grb - n) * DDIM);

    float acc[TM][TN];
#pragma unroll
    for (int m = 0; m < TM; ++m)
#pragma unroll
        for (int nn = 0; nn < TN; ++nn) acc[m][nn] = 0.f;

#pragma unroll 1
    for (int k0 = 0; k0 < DDIM; k0 += BK) {
        float4 av = *(const float4*)(pA + k0 + ka);
        float4 bv = *(const float4*)(pB + k0 + ka);
        As[ka + 0][lr] = av.x; As[ka + 1][lr] = av.y;
        As[ka + 2][lr] = av.z; As[ka + 3][lr] = av.w;
        Bs[ka + 0][lr] = bv.x; Bs[ka + 1][lr] = bv.y;
        Bs[ka + 2][lr] = bv.z; Bs[ka + 3][lr] = bv.w;
        __syncthreads();
#pragma unroll
        for (int kk = 0; kk < BK; ++kk) {
            float a[TM], b[TN];
            *(float4*)&a[0] = *(const float4*)&As[kk][ty * TM];
            *(float4*)&a[4] = *(const float4*)&As[kk][ty * TM + 4];
            *(float4*)&b[0] = *(const float4*)&Bs[kk][tx * TN];
            *(float4*)&b[4] = *(const float4*)&Bs[kk][tx * TN + 4];
#pragma unroll
            for (int m = 0; m < TM; ++m)
#pragma unroll
                for (int nn = 0; nn < TN; ++nn)
                    acc[m][nn] += a[m] * b[nn];
        }
        __syncthreads();
    }

    // ---- epilogue: l2 -> 5-bandwidth RBF -> tile sum ----
    const float inv0 = g_inv[0], inv1 = g_inv[1], inv2 = g_inv[2],
                inv3 = g_inv[3], inv4 = g_inv[4];
    float sqi[TM], sqj[TN];
    const int gi0 = row0 + ty * TM;
    const int gj0 = col0 + tx * TN;
#pragma unroll
    for (int m = 0; m < TM; ++m) sqi[m] = g_sq[gi0 + m];
#pragma unroll
    for (int nn = 0; nn < TN; ++nn) sqj[nn] = g_sq[gj0 + nn];

    float tsum = 0.f;
#pragma unroll
    for (int m = 0; m < TM; ++m) {
#pragma unroll
        for (int nn = 0; nn < TN; ++nn) {
            float l2 = fmaxf(sqi[m] + sqj[nn] - 2.f * acc[m][nn], 0.f);
            tsum += __expf(-l2 * inv0) + __expf(-l2 * inv1) +
                    __expf(-l2 * inv2) + __expf(-l2 * inv3) +
                    __expf(-l2 * inv4);
        }
    }

    // Block reduction of tsum.
    __shared__ float red[256];
    red[tid] = tsum;
    __syncthreads();
#pragma unroll
    for (int o = 128; o >= 32; o >>= 1) {
        if (tid < o) red[tid] += red[tid + o];
        __syncthreads();
    }
    if (tid < 32) {
        float v = red[tid];
#pragma unroll
        for (int o = 16; o; o >>= 1) v += __shfl_xor_sync(0xffffffffu, v, o);
        if (tid == 0) {
            int half = n / BM;
            double w;
            if (ti == tj) w = 1.0;
            else if ((ti < half) == (tj < half)) w = 2.0;
            else w = -2.0;
            atomicAdd(&g_acc, w * (double)v);
        }
    }
}

__global__ void k_final(float* out, int n) {
    if (threadIdx.x == 0)
        out[0] = (float)(g_acc / ((double)n * (double)n));
}

// ---------------------------------------------------------------------------
extern "C" void kernel_launch(void* const* d_in, const int* in_sizes, int n_in,
                              void* d_out, int out_size) {
    const float* src = (const float*)d_in[0];
    const float* tgt = (const float*)d_in[1];
    float* out = (float*)d_out;

    int n  = in_sizes[0] / DDIM;   // 4096
    int nt = 2 * n;                // 8192

    k_init<<<1, 256>>>();
    k_sq<<<nt / 8, 256>>>(src, tgt, n);
    k_colsum<<<nt / 128, DDIM>>>(src, tgt, n);
    k_bw<<<1, DDIM>>>(n);

    int numTiles = nt / BM;                       // 64
    int nBlocks  = numTiles * (numTiles + 1) / 2; // 2080
    k_main<<<nBlocks, 256>>>(src, tgt, n);

    k_final<<<1, 32>>>(out, n);
}

// round 5
// speedup vs baseline: 2.3923x; 2.3923x over previous
#include <cuda_runtime.h>
#include <cuda_bf16.h>
#include <cstdint>
#include <math.h>

#define DDIM   256
#define NROWS  8192
#define TMT    128            // tile M
#define TNT    128            // tile N
#define KC     64             // bf16 per K-chunk (128 bytes per smem row)
#define NCHUNK (DDIM / KC)    // 4
#define TILE_B 16384          // 128 rows x 128 bytes
#define SMEM_DYN (2 * 4 * TILE_B)   // 2 buffers x {Ahi,Alo,Bhi,Blo}

// ---------------- device scratch (no allocation allowed) -------------------
__device__ double g_S;
__device__ double g_colsum[DDIM];
__device__ float  g_sq[NROWS];
__device__ float  g_inv4;      // log2(e) / (bw*16)
__device__ double g_acc;
__device__ __nv_bfloat16 g_hi[(size_t)NROWS * DDIM];
__device__ __nv_bfloat16 g_lo[(size_t)NROWS * DDIM];

// ---------------- PTX helpers (all base sm_80-class, legal on sm_103) ------
__device__ __forceinline__ uint32_t smem_u32(const void* p) {
    uint32_t a;
    asm("{ .reg .u64 t; cvta.to.shared.u64 t, %1; cvt.u32.u64 %0, t; }"
        : "=r"(a) : "l"(p));
    return a;
}
__device__ __forceinline__ void ldsm4(uint32_t* r, uint32_t addr) {
    asm volatile("ldmatrix.sync.aligned.m8n8.x4.shared.b16 {%0,%1,%2,%3}, [%4];"
                 : "=r"(r[0]), "=r"(r[1]), "=r"(r[2]), "=r"(r[3]) : "r"(addr));
}
__device__ __forceinline__ void mma16816(float* c, const uint32_t* a,
                                         uint32_t b0, uint32_t b1) {
    asm volatile(
        "mma.sync.aligned.m16n8k16.row.col.f32.bf16.bf16.f32 "
        "{%0,%1,%2,%3}, {%4,%5,%6,%7}, {%8,%9}, {%0,%1,%2,%3};"
        : "+f"(c[0]), "+f"(c[1]), "+f"(c[2]), "+f"(c[3])
        : "r"(a[0]), "r"(a[1]), "r"(a[2]), "r"(a[3]), "r"(b0), "r"(b1));
}
__device__ __forceinline__ void cp16(uint32_t dst, const void* src) {
    asm volatile("cp.async.cg.shared.global [%0], [%1], 16;"
                 :: "r"(dst), "l"(__cvta_generic_to_global(src)) : "memory");
}
__device__ __forceinline__ float ex2f(float x) {
    float r;
    asm("ex2.approx.ftz.f32 %0, %1;" : "=f"(r) : "f"(x));
    return r;
}

// ---------------- small kernels ---------------------------------------------
__global__ void k_init() {
    int t = threadIdx.x;
    if (t < DDIM) g_colsum[t] = 0.0;
    if (t == 0) { g_S = 0.0; g_acc = 0.0; }
}

// warp per row: squared norm + bf16 hi/lo split
__global__ void k_prep(const float* __restrict__ src,
                       const float* __restrict__ tgt, int n) {
    int row  = blockIdx.x * 8 + (threadIdx.x >> 5);
    int lane = threadIdx.x & 31;
    const float* p = (row < n) ? (src + (size_t)row * DDIM)
                               : (tgt + (size_t)(row - n) * DDIM);
    const float4* p4 = (const float4*)p;
    float s = 0.f;
#pragma unroll
    for (int i = 0; i < 2; ++i) {
        float4 v = p4[lane + i * 32];
        s += v.x * v.x + v.y * v.y + v.z * v.z + v.w * v.w;
        __nv_bfloat16 hx = __float2bfloat16(v.x);
        __nv_bfloat16 hy = __float2bfloat16(v.y);
        __nv_bfloat16 hz = __float2bfloat16(v.z);
        __nv_bfloat16 hw = __float2bfloat16(v.w);
        __nv_bfloat16 lx = __float2bfloat16(v.x - __bfloat162float(hx));
        __nv_bfloat16 ly = __float2bfloat16(v.y - __bfloat162float(hy));
        __nv_bfloat16 lz = __float2bfloat16(v.z - __bfloat162float(hz));
        __nv_bfloat16 lw = __float2bfloat16(v.w - __bfloat162float(hw));
        size_t e0 = (size_t)row * DDIM + (lane + i * 32) * 4;
        __nv_bfloat162* H = (__nv_bfloat162*)(g_hi + e0);
        __nv_bfloat162* L = (__nv_bfloat162*)(g_lo + e0);
        __nv_bfloat162 h01; h01.x = hx; h01.y = hy;
        __nv_bfloat162 h23; h23.x = hz; h23.y = hw;
        __nv_bfloat162 l01; l01.x = lx; l01.y = ly;
        __nv_bfloat162 l23; l23.x = lz; l23.y = lw;
        H[0] = h01; H[1] = h23;
        L[0] = l01; L[1] = l23;
    }
#pragma unroll
    for (int o = 16; o; o >>= 1) s += __shfl_xor_sync(0xffffffffu, s, o);
    if (lane == 0) {
        g_sq[row] = s;
        atomicAdd(&g_S, (double)s);
    }
}

__global__ void k_colsum(const float* __restrict__ src,
                         const float* __restrict__ tgt, int n) {
    int col = threadIdx.x;
    int r0  = blockIdx.x * 128;
    double s = 0.0;
    for (int r = r0; r < r0 + 128; ++r) {
        const float* p = (r < n) ? (src + (size_t)r * DDIM)
                                 : (tgt + (size_t)(r - n) * DDIM);
        s += (double)p[col];
    }
    atomicAdd(&g_colsum[col], s);
}

// sum(L2) = 2*N*S - 2*||colsum||^2 ; bw = sum/(N^2-N)/4 ; inv4 = log2e/(bw*16)
__global__ void k_bw(int n) {
    __shared__ double sh[DDIM];
    int t = threadIdx.x;
    double v = g_colsum[t];
    sh[t] = v * v;
    __syncthreads();
    for (int o = DDIM / 2; o; o >>= 1) {
        if (t < o) sh[t] += sh[t + o];
        __syncthreads();
    }
    if (t == 0) {
        double N = 2.0 * (double)n;
        double sumL2 = 2.0 * N * g_S - 2.0 * sh[0];
        double bw = sumL2 / (N * N - N) / 4.0;
        g_inv4 = (float)(1.4426950408889634 / (bw * 16.0));
    }
}

// ---------------- main fused mma.sync kernel ---------------------------------
// Each thread copies one chunk's worth of 16B granules into swizzled smem.
// Smem tile layout: 128 rows x 128B, granule g stored at g ^ (row & 7).
__device__ __forceinline__ void copy_chunk(int c, uint32_t sbuf,
                                           int row0, int col0, int tid) {
    const __nv_bfloat16* srcs[4] = {
        g_hi, g_lo, g_hi, g_lo
    };
    int bases[4] = { row0, row0, col0, col0 };
#pragma unroll
    for (int t = 0; t < 4; ++t) {
        const __nv_bfloat16* G = srcs[t];
        int R0 = bases[t];
        uint32_t tb = sbuf + t * TILE_B;
#pragma unroll
        for (int i = 0; i < 4; ++i) {
            int idx  = i * 256 + tid;      // 0..1023 granules
            int r    = idx >> 3;
            int gcol = idx & 7;
            const void* gp = G + (size_t)(R0 + r) * DDIM + c * KC + gcol * 8;
            uint32_t soff = tb + r * 128 + (((uint32_t)(gcol ^ (r & 7))) << 4);
            cp16(soff, gp);
        }
    }
}

__device__ __forceinline__ void compute_chunk(
    uint32_t sbuf, float acc[2][8][4],
    const uint32_t aRow[2], const uint32_t bRow[4], int rs, int gb) {
#pragma unroll
    for (int ks = 0; ks < 4; ++ks) {
        int g = ks * 2 + gb;
        uint32_t swz = (uint32_t)(g ^ rs) << 4;
        uint32_t Ah[2][4], Al[2][4], Bh[4][4], Bl[4][4];
#pragma unroll
        for (int mi = 0; mi < 2; ++mi) {
            uint32_t off = aRow[mi] + swz;
            ldsm4(Ah[mi], sbuf + 0 * TILE_B + off);
            ldsm4(Al[mi], sbuf + 1 * TILE_B + off);
        }
#pragma unroll
        for (int q = 0; q < 4; ++q) {
            uint32_t off = bRow[q] + swz;
            ldsm4(Bh[q], sbuf + 2 * TILE_B + off);
            ldsm4(Bl[q], sbuf + 3 * TILE_B + off);
        }
#pragma unroll
        for (int mi = 0; mi < 2; ++mi)
#pragma unroll
            for (int q = 0; q < 4; ++q) {
                // hi*hi
                mma16816(acc[mi][2 * q + 0], Ah[mi], Bh[q][0], Bh[q][2]);
                mma16816(acc[mi][2 * q + 1], Ah[mi], Bh[q][1], Bh[q][3]);
                // hi*lo
                mma16816(acc[mi][2 * q + 0], Ah[mi], Bl[q][0], Bl[q][2]);
                mma16816(acc[mi][2 * q + 1], Ah[mi], Bl[q][1], Bl[q][3]);
                // lo*hi
                mma16816(acc[mi][2 * q + 0], Al[mi], Bh[q][0], Bh[q][2]);
                mma16816(acc[mi][2 * q + 1], Al[mi], Bh[q][1], Bh[q][3]);
            }
    }
}

__global__ void __launch_bounds__(256, 1)
k_main(int n) {
    extern __shared__ __align__(128) char smem[];
    uint32_t sb = smem_u32(smem);
    __shared__ float s_sqi[128], s_sqj[128], red[256];

    const int tid  = threadIdx.x;
    const int lane = tid & 31;
    const int w    = tid >> 5;
    const int wm   = w & 3;        // 4 row groups of 32
    const int wn   = w >> 2;       // 2 col groups of 64
    const int gid  = lane >> 2;    // groupID
    const int tig  = lane & 3;
    const int l16  = lane & 15;
    const int gb   = lane >> 4;
    const int rs   = l16 & 7;

    // triangle decode
    int L  = blockIdx.x;
    int tj = (int)((sqrtf(8.0f * (float)L + 1.0f) - 1.0f) * 0.5f);
    while ((tj + 1) * (tj + 2) / 2 <= L) ++tj;
    while (tj * (tj + 1) / 2 > L) --tj;
    int ti = L - tj * (tj + 1) / 2;
    const int row0 = ti * TMT;
    const int col0 = tj * TNT;

    if (tid < 128) {
        s_sqi[tid] = g_sq[row0 + tid];
        s_sqj[tid] = g_sq[col0 + tid];
    }

    uint32_t aRow[2], bRow[4];
#pragma unroll
    for (int mi = 0; mi < 2; ++mi)
        aRow[mi] = (uint32_t)(wm * 32 + mi * 16 + l16) * 128u;
#pragma unroll
    for (int q = 0; q < 4; ++q)
        bRow[q] = (uint32_t)(wn * 64 + q * 16 + l16) * 128u;

    float acc[2][8][4];
#pragma unroll
    for (int mi = 0; mi < 2; ++mi)
#pragma unroll
        for (int nj = 0; nj < 8; ++nj)
#pragma unroll
            for (int e = 0; e < 4; ++e) acc[mi][nj][e] = 0.f;

    // pipeline: prefetch chunk 0
    copy_chunk(0, sb, row0, col0, tid);
    asm volatile("cp.async.commit_group;" ::: "memory");

#pragma unroll
    for (int c = 0; c < NCHUNK; ++c) {
        if (c + 1 < NCHUNK) {
            copy_chunk(c + 1, sb + ((c + 1) & 1) * (4 * TILE_B), row0, col0, tid);
            asm volatile("cp.async.commit_group;" ::: "memory");
            asm volatile("cp.async.wait_group 1;" ::: "memory");
        } else {
            asm volatile("cp.async.wait_group 0;" ::: "memory");
        }
        __syncthreads();
        compute_chunk(sb + (c & 1) * (4 * TILE_B), acc, aRow, bRow, rs, gb);
        __syncthreads();
    }

    // ---- epilogue ----
    const float inv4 = g_inv4;
    float sqi_r[4];   // rows: wm*32 + gid + {0,8,16,24}
#pragma unroll
    for (int h = 0; h < 4; ++h) sqi_r[h] = s_sqi[wm * 32 + gid + h * 8];

    float tsum = 0.f;
#pragma unroll
    for (int mi = 0; mi < 2; ++mi) {
#pragma unroll
        for (int nj = 0; nj < 8; ++nj) {
            int cb = wn * 64 + nj * 8 + tig * 2;
            float sj0 = s_sqj[cb], sj1 = s_sqj[cb + 1];
#pragma unroll
            for (int e = 0; e < 4; ++e) {
                float si = sqi_r[mi * 2 + (e >> 1)];
                float sj = (e & 1) ? sj1 : sj0;
                float l2 = fmaxf(si + sj - 2.f * acc[mi][nj][e], 0.f);
                float ee = ex2f(-l2 * inv4);
                float s  = ee;         // bw*16
                ee *= ee; s += ee;     // bw*8
                ee *= ee; s += ee;     // bw*4
                ee *= ee; s += ee;     // bw*2
                ee *= ee; s += ee;     // bw
                tsum += s;
            }
        }
    }

    red[tid] = tsum;
    __syncthreads();
    if (tid < 128) red[tid] += red[tid + 128];
    __syncthreads();
    if (tid < 64) red[tid] += red[tid + 64];
    __syncthreads();
    if (tid < 32) {
        float v = red[tid] + red[tid + 32];
#pragma unroll
        for (int o = 16; o; o >>= 1) v += __shfl_xor_sync(0xffffffffu, v, o);
        if (tid == 0) {
            int half = n / TMT;
            double wgt = (ti == tj) ? 1.0
                       : (((ti < half) == (tj < half)) ? 2.0 : -2.0);
            atomicAdd(&g_acc, wgt * (double)v);
        }
    }
}

__global__ void k_final(float* out, int n) {
    if (threadIdx.x == 0)
        out[0] = (float)(g_acc / ((double)n * (double)n));
}

// ---------------------------------------------------------------------------
extern "C" void kernel_launch(void* const* d_in, const int* in_sizes, int n_in,
                              void* d_out, int out_size) {
    const float* src = (const float*)d_in[0];
    const float* tgt = (const float*)d_in[1];
    float* out = (float*)d_out;

    int n  = in_sizes[0] / DDIM;   // 4096
    int nt = 2 * n;                // 8192

    cudaFuncSetAttribute(k_main, cudaFuncAttributeMaxDynamicSharedMemorySize,
                         SMEM_DYN);

    k_init<<<1, 256>>>();
    k_prep<<<nt / 8, 256>>>(src, tgt, n);
    k_colsum<<<nt / 128, DDIM>>>(src, tgt, n);
    k_bw<<<1, DDIM>>>(n);

    int numTiles = nt / TMT;                      // 64
    int nBlocks  = numTiles * (numTiles + 1) / 2; // 2080
    k_main<<<nBlocks, 256, SMEM_DYN>>>(n);

    k_final<<<1, 32>>>(out, n);
}

// round 6
// speedup vs baseline: 4.7218x; 1.9738x over previous
#include <cuda_runtime.h>
#include <cuda_bf16.h>
#include <cstdint>
#include <math.h>

#define DDIM   256
#define NROWS  8192
#define TMT    128            // tile M
#define TNT    128            // tile N
#define KC     64             // bf16 per K-chunk (128 bytes per smem row)
#define NCHUNK (DDIM / KC)    // 4
#define TILE_B 16384          // 128 rows x 128 bytes
#define SMEM_DYN (2 * 2 * TILE_B)   // 2 stages x {A, B} = 64 KB

// ---------------- device scratch (no allocation allowed) -------------------
__device__ double g_S;
__device__ double g_colsum[DDIM];
__device__ float  g_sq[NROWS];
__device__ float  g_inv4;      // log2(e) / (bw*16)
__device__ double g_acc;
__device__ __nv_bfloat16 g_bf[(size_t)NROWS * DDIM];

// ---------------- PTX helpers (base sm_80-class, legal on sm_103) ----------
__device__ __forceinline__ uint32_t smem_u32(const void* p) {
    uint32_t a;
    asm("{ .reg .u64 t; cvta.to.shared.u64 t, %1; cvt.u32.u64 %0, t; }"
        : "=r"(a) : "l"(p));
    return a;
}
__device__ __forceinline__ void ldsm4(uint32_t* r, uint32_t addr) {
    asm volatile("ldmatrix.sync.aligned.m8n8.x4.shared.b16 {%0,%1,%2,%3}, [%4];"
                 : "=r"(r[0]), "=r"(r[1]), "=r"(r[2]), "=r"(r[3]) : "r"(addr));
}
__device__ __forceinline__ void mma16816(float* c, const uint32_t* a,
                                         uint32_t b0, uint32_t b1) {
    asm volatile(
        "mma.sync.aligned.m16n8k16.row.col.f32.bf16.bf16.f32 "
        "{%0,%1,%2,%3}, {%4,%5,%6,%7}, {%8,%9}, {%0,%1,%2,%3};"
        : "+f"(c[0]), "+f"(c[1]), "+f"(c[2]), "+f"(c[3])
        : "r"(a[0]), "r"(a[1]), "r"(a[2]), "r"(a[3]), "r"(b0), "r"(b1));
}
__device__ __forceinline__ void cp16(uint32_t dst, const void* src) {
    asm volatile("cp.async.cg.shared.global [%0], [%1], 16;"
                 :: "r"(dst), "l"(__cvta_generic_to_global(src)) : "memory");
}
__device__ __forceinline__ float ex2f(float x) {
    float r;
    asm("ex2.approx.ftz.f32 %0, %1;" : "=f"(r) : "f"(x));
    return r;
}

// ---------------- small kernels ---------------------------------------------
__global__ void k_init() {
    int t = threadIdx.x;
    if (t < DDIM) g_colsum[t] = 0.0;
    if (t == 0) { g_S = 0.0; g_acc = 0.0; }
}

// warp per row: squared norm (fp32, exact) + bf16 round
__global__ void k_prep(const float* __restrict__ src,
                       const float* __restrict__ tgt, int n) {
    int row  = blockIdx.x * 8 + (threadIdx.x >> 5);
    int lane = threadIdx.x & 31;
    const float* p = (row < n) ? (src + (size_t)row * DDIM)
                               : (tgt + (size_t)(row - n) * DDIM);
    const float4* p4 = (const float4*)p;
    float s = 0.f;
#pragma unroll
    for (int i = 0; i < 2; ++i) {
        float4 v = p4[lane + i * 32];
        s += v.x * v.x + v.y * v.y + v.z * v.z + v.w * v.w;
        __nv_bfloat162 b01 = __floats2bfloat162_rn(v.x, v.y);
        __nv_bfloat162 b23 = __floats2bfloat162_rn(v.z, v.w);
        size_t e0 = (size_t)row * DDIM + (lane + i * 32) * 4;
        __nv_bfloat162* H = (__nv_bfloat162*)(g_bf + e0);
        H[0] = b01; H[1] = b23;
    }
#pragma unroll
    for (int o = 16; o; o >>= 1) s += __shfl_xor_sync(0xffffffffu, s, o);
    if (lane == 0) {
        g_sq[row] = s;
        atomicAdd(&g_S, (double)s);
    }
}

__global__ void k_colsum(const float* __restrict__ src,
                         const float* __restrict__ tgt, int n) {
    int col = threadIdx.x;
    int r0  = blockIdx.x * 128;
    double s = 0.0;
    for (int r = r0; r < r0 + 128; ++r) {
        const float* p = (r < n) ? (src + (size_t)r * DDIM)
                                 : (tgt + (size_t)(r - n) * DDIM);
        s += (double)p[col];
    }
    atomicAdd(&g_colsum[col], s);
}

// sum(L2) = 2*N*S - 2*||colsum||^2 ; bw = sum/(N^2-N)/4 ; inv4 = log2e/(bw*16)
__global__ void k_bw(int n) {
    __shared__ double sh[DDIM];
    int t = threadIdx.x;
    double v = g_colsum[t];
    sh[t] = v * v;
    __syncthreads();
    for (int o = DDIM / 2; o; o >>= 1) {
        if (t < o) sh[t] += sh[t + o];
        __syncthreads();
    }
    if (t == 0) {
        double N = 2.0 * (double)n;
        double sumL2 = 2.0 * N * g_S - 2.0 * sh[0];
        double bw = sumL2 / (N * N - N) / 4.0;
        g_inv4 = (float)(1.4426950408889634 / (bw * 16.0));
    }
}

// ---------------- main fused mma.sync kernel ---------------------------------
// Smem tile layout: 128 rows x 128B, 16B granule g stored at g ^ (row & 7).
__device__ __forceinline__ void copy_chunk(int c, uint32_t sbuf,
                                           int row0, int col0, int tid) {
    int bases[2] = { row0, col0 };
#pragma unroll
    for (int t = 0; t < 2; ++t) {
        int R0 = bases[t];
        uint32_t tb = sbuf + t * TILE_B;
#pragma unroll
        for (int i = 0; i < 4; ++i) {
            int idx  = i * 256 + tid;      // 0..1023 granules
            int r    = idx >> 3;
            int gcol = idx & 7;
            const void* gp = g_bf + (size_t)(R0 + r) * DDIM + c * KC + gcol * 8;
            uint32_t soff = tb + r * 128 + (((uint32_t)(gcol ^ (r & 7))) << 4);
            cp16(soff, gp);
        }
    }
}

__device__ __forceinline__ void compute_chunk(
    uint32_t sbuf, float acc[2][8][4],
    const uint32_t aRow[2], const uint32_t bRow[4], int rs, int gb) {
#pragma unroll
    for (int ks = 0; ks < 4; ++ks) {
        int g = ks * 2 + gb;
        uint32_t swz = (uint32_t)(g ^ rs) << 4;
        uint32_t A[2][4], Bm[4][4];
#pragma unroll
        for (int mi = 0; mi < 2; ++mi)
            ldsm4(A[mi], sbuf + 0 * TILE_B + aRow[mi] + swz);
#pragma unroll
        for (int q = 0; q < 4; ++q)
            ldsm4(Bm[q], sbuf + 1 * TILE_B + bRow[q] + swz);
#pragma unroll
        for (int mi = 0; mi < 2; ++mi)
#pragma unroll
            for (int q = 0; q < 4; ++q) {
                mma16816(acc[mi][2 * q + 0], A[mi], Bm[q][0], Bm[q][2]);
                mma16816(acc[mi][2 * q + 1], A[mi], Bm[q][1], Bm[q][3]);
            }
    }
}

__global__ void __launch_bounds__(256, 2)
k_main(int n) {
    extern __shared__ __align__(128) char smem[];
    uint32_t sb = smem_u32(smem);
    __shared__ float s_sqi[128], s_sqj[128], red[256];

    const int tid  = threadIdx.x;
    const int lane = tid & 31;
    const int w    = tid >> 5;
    const int wm   = w & 3;        // 4 row groups of 32
    const int wn   = w >> 2;       // 2 col groups of 64
    const int gid  = lane >> 2;    // groupID
    const int tig  = lane & 3;
    const int l16  = lane & 15;
    const int gb   = lane >> 4;
    const int rs   = l16 & 7;

    // triangle decode
    int L  = blockIdx.x;
    int tj = (int)((sqrtf(8.0f * (float)L + 1.0f) - 1.0f) * 0.5f);
    while ((tj + 1) * (tj + 2) / 2 <= L) ++tj;
    while (tj * (tj + 1) / 2 > L) --tj;
    int ti = L - tj * (tj + 1) / 2;
    const int row0 = ti * TMT;
    const int col0 = tj * TNT;

    if (tid < 128) {
        s_sqi[tid] = g_sq[row0 + tid];
        s_sqj[tid] = g_sq[col0 + tid];
    }

    uint32_t aRow[2], bRow[4];
#pragma unroll
    for (int mi = 0; mi < 2; ++mi)
        aRow[mi] = (uint32_t)(wm * 32 + mi * 16 + l16) * 128u;
#pragma unroll
    for (int q = 0; q < 4; ++q)
        bRow[q] = (uint32_t)(wn * 64 + q * 16 + l16) * 128u;

    float acc[2][8][4];
#pragma unroll
    for (int mi = 0; mi < 2; ++mi)
#pragma unroll
        for (int nj = 0; nj < 8; ++nj)
#pragma unroll
            for (int e = 0; e < 4; ++e) acc[mi][nj][e] = 0.f;

    // pipeline: prefetch chunk 0
    copy_chunk(0, sb, row0, col0, tid);
    asm volatile("cp.async.commit_group;" ::: "memory");

#pragma unroll
    for (int c = 0; c < NCHUNK; ++c) {
        if (c + 1 < NCHUNK) {
            copy_chunk(c + 1, sb + ((c + 1) & 1) * (2 * TILE_B), row0, col0, tid);
            asm volatile("cp.async.commit_group;" ::: "memory");
            asm volatile("cp.async.wait_group 1;" ::: "memory");
        } else {
            asm volatile("cp.async.wait_group 0;" ::: "memory");
        }
        __syncthreads();
        compute_chunk(sb + (c & 1) * (2 * TILE_B), acc, aRow, bRow, rs, gb);
        __syncthreads();
    }

    // ---- epilogue ----
    const float inv4 = g_inv4;
    float sqi_r[4];   // rows: wm*32 + gid + {0,8,16,24}
#pragma unroll
    for (int h = 0; h < 4; ++h) sqi_r[h] = s_sqi[wm * 32 + gid + h * 8];

    float tsum = 0.f;
#pragma unroll
    for (int mi = 0; mi < 2; ++mi) {
#pragma unroll
        for (int nj = 0; nj < 8; ++nj) {
            int cb = wn * 64 + nj * 8 + tig * 2;
            float sj0 = s_sqj[cb], sj1 = s_sqj[cb + 1];
#pragma unroll
            for (int e = 0; e < 4; ++e) {
                float si = sqi_r[mi * 2 + (e >> 1)];
                float sj = (e & 1) ? sj1 : sj0;
                float l2 = fmaxf(si + sj - 2.f * acc[mi][nj][e], 0.f);
                float ee = ex2f(-l2 * inv4);
                float s  = ee;         // bw*16
                ee *= ee; s += ee;     // bw*8
                ee *= ee; s += ee;     // bw*4
                ee *= ee; s += ee;     // bw*2
                ee *= ee; s += ee;     // bw
                tsum += s;
            }
        }
    }

    red[tid] = tsum;
    __syncthreads();
    if (tid < 128) red[tid] += red[tid + 128];
    __syncthreads();
    if (tid < 64) red[tid] += red[tid + 64];
    __syncthreads();
    if (tid < 32) {
        float v = red[tid] + red[tid + 32];
#pragma unroll
        for (int o = 16; o; o >>= 1) v += __shfl_xor_sync(0xffffffffu, v, o);
        if (tid == 0) {
            int half = n / TMT;
            double wgt = (ti == tj) ? 1.0
                       : (((ti < half) == (tj < half)) ? 2.0 : -2.0);
            atomicAdd(&g_acc, wgt * (double)v);
        }
    }
}

__global__ void k_final(float* out, int n) {
    if (threadIdx.x == 0)
        out[0] = (float)(g_acc / ((double)n * (double)n));
}

// ---------------------------------------------------------------------------
extern "C" void kernel_launch(void* const* d_in, const int* in_sizes, int n_in,
                              void* d_out, int out_size) {
    const float* src = (const float*)d_in[0];
    const float* tgt = (const float*)d_in[1];
    float* out = (float*)d_out;

    int n  = in_sizes[0] / DDIM;   // 4096
    int nt = 2 * n;                // 8192

    cudaFuncSetAttribute(k_main, cudaFuncAttributeMaxDynamicSharedMemorySize,
                         SMEM_DYN);

    k_init<<<1, 256>>>();
    k_prep<<<nt / 8, 256>>>(src, tgt, n);
    k_colsum<<<nt / 128, DDIM>>>(src, tgt, n);
    k_bw<<<1, DDIM>>>(n);

    int numTiles = nt / TMT;                      // 64
    int nBlocks  = numTiles * (numTiles + 1) / 2; // 2080
    k_main<<<nBlocks, 256, SMEM_DYN>>>(n);

    k_final<<<1, 32>>>(out, n);
}